// round 8
// baseline (speedup 1.0000x reference)
#include <cuda_runtime.h>
#include <cstdint>

#define N_DIM 16384
#define D_DIM 10240
#define C_DIM 128
#define KC 32                    // k per chunk
#define NCHUNK (D_DIM / KC)      // 320
#define M_TILE 64
#define THREADS 256

// Device-resolved input bindings (selector kernel writes these).
__device__ const float* g_x;
__device__ const float* g_am;

// One thread: am rows are exactly +/-1; x is continuous normal.
__global__ void select_inputs_kernel(const float* a, const float* b) {
    bool a_is_am = true;
    for (int i = 0; i < 64; ++i) {
        float v = a[i];
        if (v != 1.0f && v != -1.0f) { a_is_am = false; break; }
    }
    g_x  = a_is_am ? b : a;
    g_am = a_is_am ? a : b;
}

__global__ void __launch_bounds__(THREADS)
hd_simple_kernel(float* __restrict__ out) {
    // phase1: xs[KC][64] (2048 f) + as[KC][128] (4096 f) = 6144 floats
    // phase2: S[64][132] = 8448 floats (reused)
    __shared__ __align__(16) float smem[8448];
    float* xs = smem;                 // [KC][64]  k-major
    float* as_ = smem + KC * M_TILE;  // [KC][128] k-major

    const float* __restrict__ x  = g_x;
    const float* __restrict__ am = g_am;

    const int tid = threadIdx.x;
    const int tx = tid & 15;          // class group: classes tx*8 .. tx*8+7
    const int ty = tid >> 4;          // row group:   rows    ty*4 .. ty*4+3
    const int row0 = blockIdx.x * M_TILE;

    // loader mapping: unit u = tid + p*256 -> row/class = u>>3, k4 = u&7
    const int lr = tid >> 3;          // 0..31
    const int lk4 = tid & 7;          // 0..7  (k = lk4*4 .. +3)

    float acc[4][8];
#pragma unroll
    for (int i = 0; i < 4; ++i)
#pragma unroll
        for (int j = 0; j < 8; ++j) acc[i][j] = 0.0f;

    float4 xv[2], av[4];
    const float* xbase = x + (size_t)row0 * D_DIM;

#pragma unroll
    for (int p = 0; p < 2; ++p)
        xv[p] = *(const float4*)(xbase + (size_t)(lr + p * 32) * D_DIM + lk4 * 4);
#pragma unroll
    for (int p = 0; p < 4; ++p)
        av[p] = *(const float4*)(am + (size_t)(lr + p * 32) * D_DIM + lk4 * 4);

    for (int ch = 0; ch < NCHUNK; ++ch) {
        __syncthreads();   // previous chunk's smem reads complete

        // store regs -> smem transposed (k-major)
#pragma unroll
        for (int p = 0; p < 2; ++p) {
            int r = lr + p * 32;
            xs[(lk4 * 4 + 0) * M_TILE + r] = xv[p].x;
            xs[(lk4 * 4 + 1) * M_TILE + r] = xv[p].y;
            xs[(lk4 * 4 + 2) * M_TILE + r] = xv[p].z;
            xs[(lk4 * 4 + 3) * M_TILE + r] = xv[p].w;
        }
#pragma unroll
        for (int p = 0; p < 4; ++p) {
            int c = lr + p * 32;
            as_[(lk4 * 4 + 0) * C_DIM + c] = av[p].x;
            as_[(lk4 * 4 + 1) * C_DIM + c] = av[p].y;
            as_[(lk4 * 4 + 2) * C_DIM + c] = av[p].z;
            as_[(lk4 * 4 + 3) * C_DIM + c] = av[p].w;
        }
        __syncthreads();

        // prefetch next chunk
        if (ch + 1 < NCHUNK) {
            const int ko = (ch + 1) * KC + lk4 * 4;
#pragma unroll
            for (int p = 0; p < 2; ++p)
                xv[p] = *(const float4*)(xbase + (size_t)(lr + p * 32) * D_DIM + ko);
#pragma unroll
            for (int p = 0; p < 4; ++p)
                av[p] = *(const float4*)(am + (size_t)(lr + p * 32) * D_DIM + ko);
        }

        // compute: 32 k-steps, 4x8 register tile
#pragma unroll
        for (int k = 0; k < KC; ++k) {
            float4 xq = *(const float4*)(xs + k * M_TILE + ty * 4);
            float4 a0 = *(const float4*)(as_ + k * C_DIM + tx * 8);
            float4 a1 = *(const float4*)(as_ + k * C_DIM + tx * 8 + 4);
            float xr[4] = {xq.x, xq.y, xq.z, xq.w};
            float ar[8] = {a0.x, a0.y, a0.z, a0.w, a1.x, a1.y, a1.z, a1.w};
#pragma unroll
            for (int i = 0; i < 4; ++i)
#pragma unroll
                for (int j = 0; j < 8; ++j)
                    acc[i][j] = fmaf(xr[i], ar[j], acc[i][j]);
        }
    }

    // ---- epilogue: sims -> smem, per-row first-max argmax ----
    __syncthreads();                  // compute-phase smem reads done
    float* S = smem;                  // [64][132]
#pragma unroll
    for (int i = 0; i < 4; ++i)
#pragma unroll
        for (int j = 0; j < 8; ++j)
            S[(ty * 4 + i) * 132 + tx * 8 + j] = acc[i][j];
    __syncthreads();

    if (tid < M_TILE) {
        const float* rowp = S + tid * 132;
        float best = rowp[0];
        int bi = 0;
#pragma unroll 4
        for (int c = 1; c < C_DIM; ++c) {
            float v = rowp[c];
            if (v > best) { best = v; bi = c; }   // first max, like jnp.argmax
        }
        // __output__ dtype is float32: write the prediction as a float value.
        out[row0 + tid] = (float)bi;
    }
}

extern "C" void kernel_launch(void* const* d_in, const int* in_sizes, int n_in,
                              void* d_out, int out_size) {
    // Shapes are fixed by the problem definition (N=16384, D=10240, C=128).
    // Resolve x/am identity on-device (am is exactly +/-1 everywhere).
    const float* a = (const float*)d_in[0];
    const float* b = (const float*)d_in[1];

    select_inputs_kernel<<<1, 1>>>(a, b);
    hd_simple_kernel<<<N_DIM / M_TILE, THREADS>>>((float*)d_out);
}

// round 9
// speedup vs baseline: 3.1523x; 3.1523x over previous
#include <cuda_runtime.h>
#include <cuda_bf16.h>
#include <cstdint>

#define N_DIM 16384
#define D_DIM 10240
#define C_DIM 128
#define NUM_CHUNK 160           // chunks of 64 k
#define NUM_KSTEP 640           // k16 steps total
#define THREADS 256
#define BSTRIDE 160             // smem bytes per class row (128 data + 32 pad)

// Device-resolved input bindings (selector kernel writes these).
__device__ const float* g_x;
__device__ const float* g_am;

__global__ void select_inputs_kernel(const float* a, const float* b) {
    bool a_is_am = true;
    for (int i = 0; i < 64; ++i) {
        float v = a[i];
        if (v != 1.0f && v != -1.0f) { a_is_am = false; break; }
    }
    g_x  = a_is_am ? b : a;
    g_am = a_is_am ? a : b;
}

static __device__ __forceinline__ uint32_t smem_u32(const void* p) {
    uint32_t a;
    asm("{ .reg .u64 t; cvta.to.shared.u64 t, %1; cvt.u32.u64 %0, t; }" : "=r"(a) : "l"(p));
    return a;
}
// cvt.rn.bf16x2.f32 d, a, b : a -> upper 16, b -> lower 16
static __device__ __forceinline__ uint32_t bf16x2_rn(float hi_f, float lo_f) {
    uint32_t r;
    asm("cvt.rn.bf16x2.f32 %0, %1, %2;" : "=r"(r) : "f"(hi_f), "f"(lo_f));
    return r;
}
// 3-way exact split of a float2 into bf16x2 hi/mid/lo (lo16 = .x, hi16 = .y)
static __device__ __forceinline__ void split3(float2 v, uint32_t& h, uint32_t& m, uint32_t& lo) {
    h = bf16x2_rn(v.y, v.x);
    float h0 = __uint_as_float(h << 16);
    float h1 = __uint_as_float(h & 0xffff0000u);
    float r0 = v.x - h0, r1 = v.y - h1;            // exact
    m = bf16x2_rn(r1, r0);
    float m0 = __uint_as_float(m << 16);
    float m1 = __uint_as_float(m & 0xffff0000u);
    lo = bf16x2_rn(r1 - m1, r0 - m0);              // exact residual rounded
}

#define MMA16816(d, a0_, a1_, a2_, a3_, b0_, b1_)                                 \
    asm volatile("mma.sync.aligned.m16n8k16.row.col.f32.bf16.bf16.f32 "           \
                 "{%0,%1,%2,%3}, {%4,%5,%6,%7}, {%8,%9}, {%0,%1,%2,%3};"          \
                 : "+f"((d)[0]), "+f"((d)[1]), "+f"((d)[2]), "+f"((d)[3])         \
                 : "r"(a0_), "r"(a1_), "r"(a2_), "r"(a3_), "r"(b0_), "r"(b1_))

__global__ void __launch_bounds__(THREADS, 1)
hd_mma_kernel(float* __restrict__ out) {
    // B tile for one 64-k chunk: class c, kstep ks (0..3), slot s (0..3).
    // slot s holds bf16 elements {k=ks*16+2s, +1, ks*16+2s+8, +9} as 8 bytes.
    __shared__ __align__(16) char smb[C_DIM * BSTRIDE];
    const uint32_t sb = smem_u32(smb);

    const float* __restrict__ x  = g_x;
    const float* __restrict__ am = g_am;

    const int tid = threadIdx.x;
    const int w = tid >> 5, l = tid & 31;
    const int lg = l >> 2;        // lane group = row within m16 tile (PTX A frag)
    const int lt = l & 3;         // thread in group (PTX A frag)

    // ---- A: direct-gmem fragment pointers (PTX m16n8k16 A layout) ----
    const float* pr0 = x + ((size_t)blockIdx.x * 128 + w * 16 + lg) * D_DIM + lt * 2;
    const float* pr8 = pr0 + (size_t)8 * D_DIM;

    // ---- B producer mapping: unit u = tid + i*256 -> c = (tid>>4)+16i,
    //      ks = (tid>>2)&3, s = tid&3 (ks, s independent of i) ----
    const int c0 = tid >> 4;
    const int ks0 = (tid >> 2) & 3;
    const int s0 = tid & 3;
    const float* bsrc0 = am + (size_t)c0 * D_DIM + ks0 * 16 + s0 * 2;
    const uint32_t bdst0 = sb + (uint32_t)(c0 * BSTRIDE + ks0 * 32 + s0 * 8);

    float acc[16][4];
#pragma unroll
    for (int n = 0; n < 16; ++n)
#pragma unroll
        for (int e = 0; e < 4; ++e) acc[n][e] = 0.0f;

    // B register prefetch (one chunk ahead): elems {k, k+1} and {k+8, k+9}
    float2 bA[8], bB[8];
#pragma unroll
    for (int i = 0; i < 8; ++i) {
        const float* s = bsrc0 + (size_t)i * 16 * D_DIM;
        bA[i] = *(const float2*)(s);
        bB[i] = *(const float2*)(s + 8);
    }

    // A double buffer (kstep granularity; col for kstep g is g*16)
    float2 va0 = *(const float2*)(pr0);
    float2 va1 = *(const float2*)(pr8);
    float2 va2 = *(const float2*)(pr0 + 8);
    float2 va3 = *(const float2*)(pr8 + 8);

    for (int ch = 0; ch < NUM_CHUNK; ++ch) {
        __syncthreads();   // prior chunk's LDS reads complete
#pragma unroll
        for (int i = 0; i < 8; ++i) {
            uint32_t p0 = bf16x2_rn(bA[i].y, bA[i].x);   // lo16 = first elem
            uint32_t p1 = bf16x2_rn(bB[i].y, bB[i].x);
            asm volatile("st.shared.v2.b32 [%0], {%1, %2};"
                         :: "r"(bdst0 + (uint32_t)(i * 16 * BSTRIDE)), "r"(p0), "r"(p1)
                         : "memory");
        }
        __syncthreads();

        if (ch + 1 < NUM_CHUNK) {
#pragma unroll
            for (int i = 0; i < 8; ++i) {
                const float* s = bsrc0 + (size_t)i * 16 * D_DIM + (ch + 1) * 64;
                bA[i] = *(const float2*)(s);
                bB[i] = *(const float2*)(s + 8);
            }
        }

#pragma unroll
        for (int ks = 0; ks < 4; ++ks) {
            const int g = ch * 4 + ks;
            float2 vb0, vb1, vb2, vb3;
            if (g + 1 < NUM_KSTEP) {
                const int off = (g + 1) * 16;
                vb0 = *(const float2*)(pr0 + off);
                vb1 = *(const float2*)(pr8 + off);
                vb2 = *(const float2*)(pr0 + off + 8);
                vb3 = *(const float2*)(pr8 + off + 8);
            } else {
                vb0 = va0; vb1 = va1; vb2 = va2; vb3 = va3;
            }

            // A frags: a0={r,k}=va0, a1={r+8,k}=va1, a2={r,k+8}=va2, a3={r+8,k+8}=va3
            uint32_t ah[4], amm[4], alo[4];
            split3(va0, ah[0], amm[0], alo[0]);
            split3(va1, ah[1], amm[1], alo[1]);
            split3(va2, ah[2], amm[2], alo[2]);
            split3(va3, ah[3], amm[3], alo[3]);

            const uint32_t bbase = sb + (uint32_t)(ks * 32 + lt * 8);
#pragma unroll
            for (int n = 0; n < 16; ++n) {
                const int c = n * 8 + lg;          // B frag: col = lane group (PTX)
                uint32_t b0, b1;
                asm volatile("ld.shared.v2.b32 {%0, %1}, [%2];"
                             : "=r"(b0), "=r"(b1)
                             : "r"(bbase + (uint32_t)(c * BSTRIDE)));
                MMA16816(acc[n], ah[0], ah[1], ah[2], ah[3], b0, b1);
                MMA16816(acc[n], amm[0], amm[1], amm[2], amm[3], b0, b1);
                MMA16816(acc[n], alo[0], alo[1], alo[2], alo[3], b0, b1);
            }
            va0 = vb0; va1 = vb1; va2 = vb2; va3 = vb3;
        }
    }

    // ---- epilogue: per-row first-max argmax over 128 classes ----
    // acc[n][e]: row = w*16 + (e<2 ? lg : lg+8), col = n*8 + lt*2 + (e&1)
#pragma unroll
    for (int h = 0; h < 2; ++h) {
        float best = -3.402823466e38f;
        int bi = 0;
#pragma unroll
        for (int n = 0; n < 16; ++n)
#pragma unroll
            for (int e = 0; e < 2; ++e) {
                float v = acc[n][h * 2 + e];
                int c = n * 8 + lt * 2 + e;
                if (v > best) { best = v; bi = c; }
            }
        // reduce across the 4 lanes (lt 0..3) sharing this row, first-max tie-break
#pragma unroll
        for (int ofs = 1; ofs < 4; ofs <<= 1) {
            float ov = __shfl_xor_sync(0xffffffffu, best, ofs);
            int oi = __shfl_xor_sync(0xffffffffu, bi, ofs);
            if (ov > best || (ov == best && oi < bi)) { best = ov; bi = oi; }
        }
        if (lt == 0)
            out[blockIdx.x * 128 + w * 16 + h * 8 + lg] = (float)bi;  // float32 output!
    }
}

extern "C" void kernel_launch(void* const* d_in, const int* in_sizes, int n_in,
                              void* d_out, int out_size) {
    const float* a = (const float*)d_in[0];
    const float* b = (const float*)d_in[1];

    select_inputs_kernel<<<1, 1>>>(a, b);
    hd_mma_kernel<<<N_DIM / 128, THREADS>>>((float*)d_out);
}

// round 10
// speedup vs baseline: 5.1943x; 1.6478x over previous
#include <cuda_runtime.h>
#include <cuda_fp16.h>
#include <cstdint>

#define N_DIM 16384
#define D_DIM 10240
#define C_DIM 128
#define NUM_CHUNK 160           // chunks of 64 k
#define NUM_KSTEP 640           // k16 steps total
#define THREADS 256
#define BSTRIDE 160             // smem bytes per class row (128 data + 32 pad)

// Device-resolved input bindings (selector kernel writes these).
__device__ const float* g_x;
__device__ const float* g_am;

__global__ void select_inputs_kernel(const float* a, const float* b) {
    bool a_is_am = true;
    for (int i = 0; i < 64; ++i) {
        float v = a[i];
        if (v != 1.0f && v != -1.0f) { a_is_am = false; break; }
    }
    g_x  = a_is_am ? b : a;
    g_am = a_is_am ? a : b;
}

static __device__ __forceinline__ uint32_t smem_u32(const void* p) {
    uint32_t a;
    asm("{ .reg .u64 t; cvta.to.shared.u64 t, %1; cvt.u32.u64 %0, t; }" : "=r"(a) : "l"(p));
    return a;
}
// pack two fp32 -> f16x2 (lo16 = v.x, hi16 = v.y)
static __device__ __forceinline__ uint32_t f16x2_rn(float2 v) {
    __half2 h2 = __float22half2_rn(v);
    return reinterpret_cast<uint32_t&>(h2);
}
// 2-way exact split of a float2 into f16x2 hi/mid; residual <= 2^-23 |x|
static __device__ __forceinline__ void split2(float2 v, uint32_t& h, uint32_t& m) {
    __half2 h2 = __float22half2_rn(v);
    float2 hf = __half22float2(h2);
    __half2 m2 = __float22half2_rn(make_float2(v.x - hf.x, v.y - hf.y));
    h = reinterpret_cast<uint32_t&>(h2);
    m = reinterpret_cast<uint32_t&>(m2);
}

#define MMA16816(d, a0_, a1_, a2_, a3_, b0_, b1_)                                 \
    asm volatile("mma.sync.aligned.m16n8k16.row.col.f32.f16.f16.f32 "             \
                 "{%0,%1,%2,%3}, {%4,%5,%6,%7}, {%8,%9}, {%0,%1,%2,%3};"          \
                 : "+f"((d)[0]), "+f"((d)[1]), "+f"((d)[2]), "+f"((d)[3])         \
                 : "r"(a0_), "r"(a1_), "r"(a2_), "r"(a3_), "r"(b0_), "r"(b1_))

__global__ void __launch_bounds__(THREADS, 1)
hd_mma_kernel(float* __restrict__ out) {
    // B tile for one 64-k chunk: class c, kstep ks (0..3), slot s (0..3).
    // slot s holds fp16 elements {k=ks*16+2s, +1, ks*16+2s+8, +9} as 8 bytes.
    __shared__ __align__(16) char smb[C_DIM * BSTRIDE];
    const uint32_t sb = smem_u32(smb);

    const float* __restrict__ x  = g_x;
    const float* __restrict__ am = g_am;

    const int tid = threadIdx.x;
    const int w = tid >> 5, l = tid & 31;
    const int lg = l >> 2;        // lane group = row within m16 tile (PTX A frag)
    const int lt = l & 3;         // thread in group (PTX A frag)

    // ---- A: direct-gmem fragment pointers (PTX m16n8k16 A layout) ----
    const float* pr0 = x + ((size_t)blockIdx.x * 128 + w * 16 + lg) * D_DIM + lt * 2;
    const float* pr8 = pr0 + (size_t)8 * D_DIM;

    // ---- B producer mapping ----
    const int c0 = tid >> 4;
    const int ks0 = (tid >> 2) & 3;
    const int s0 = tid & 3;
    const float* bsrc0 = am + (size_t)c0 * D_DIM + ks0 * 16 + s0 * 2;
    const uint32_t bdst0 = sb + (uint32_t)(c0 * BSTRIDE + ks0 * 32 + s0 * 8);

    float acc[16][4];
#pragma unroll
    for (int n = 0; n < 16; ++n)
#pragma unroll
        for (int e = 0; e < 4; ++e) acc[n][e] = 0.0f;

    // B register prefetch (one chunk ahead): elems {k,k+1} and {k+8,k+9}
    float2 bA[8], bB[8];
#pragma unroll
    for (int i = 0; i < 8; ++i) {
        const float* s = bsrc0 + (size_t)i * 16 * D_DIM;
        bA[i] = *(const float2*)(s);
        bB[i] = *(const float2*)(s + 8);
    }

    // A double buffer (kstep granularity)
    float2 va0 = *(const float2*)(pr0);
    float2 va1 = *(const float2*)(pr8);
    float2 va2 = *(const float2*)(pr0 + 8);
    float2 va3 = *(const float2*)(pr8 + 8);

    for (int ch = 0; ch < NUM_CHUNK; ++ch) {
        __syncthreads();   // prior chunk's LDS reads complete
#pragma unroll
        for (int i = 0; i < 8; ++i) {
            uint32_t p0 = f16x2_rn(bA[i]);   // am is +/-1: fp16 exact
            uint32_t p1 = f16x2_rn(bB[i]);
            asm volatile("st.shared.v2.b32 [%0], {%1, %2};"
                         :: "r"(bdst0 + (uint32_t)(i * 16 * BSTRIDE)), "r"(p0), "r"(p1)
                         : "memory");
        }
        __syncthreads();

        if (ch + 1 < NUM_CHUNK) {
#pragma unroll
            for (int i = 0; i < 8; ++i) {
                const float* s = bsrc0 + (size_t)i * 16 * D_DIM + (ch + 1) * 64;
                bA[i] = *(const float2*)(s);
                bB[i] = *(const float2*)(s + 8);
            }
        }

#pragma unroll
        for (int ks = 0; ks < 4; ++ks) {
            const int g = ch * 4 + ks;
            float2 vb0, vb1, vb2, vb3;
            if (g + 1 < NUM_KSTEP) {
                const int off = (g + 1) * 16;
                vb0 = *(const float2*)(pr0 + off);
                vb1 = *(const float2*)(pr8 + off);
                vb2 = *(const float2*)(pr0 + off + 8);
                vb3 = *(const float2*)(pr8 + off + 8);
            } else {
                vb0 = va0; vb1 = va1; vb2 = va2; vb3 = va3;
            }

            // Load ALL 16 B fragment pairs into registers (one LDS.v2 each)
            uint32_t breg[32];
            const uint32_t bbase = sb + (uint32_t)(ks * 32 + lt * 8);
#pragma unroll
            for (int n = 0; n < 16; ++n) {
                const int c = n * 8 + lg;          // B frag: col = lane group (PTX)
                asm volatile("ld.shared.v2.b32 {%0, %1}, [%2];"
                             : "=r"(breg[2 * n]), "=r"(breg[2 * n + 1])
                             : "r"(bbase + (uint32_t)(c * BSTRIDE)));
            }

            // A frags: a0={r,k}=va0, a1={r+8,k}=va1, a2={r,k+8}=va2, a3={r+8,k+8}=va3
            uint32_t ah[4], amd[4];
            split2(va0, ah[0], amd[0]);
            split2(va1, ah[1], amd[1]);
            split2(va2, ah[2], amd[2]);
            split2(va3, ah[3], amd[3]);

            // split-outer / n-inner: consecutive MMAs hit distinct accumulators
#pragma unroll
            for (int n = 0; n < 16; ++n)
                MMA16816(acc[n], ah[0], ah[1], ah[2], ah[3], breg[2 * n], breg[2 * n + 1]);
#pragma unroll
            for (int n = 0; n < 16; ++n)
                MMA16816(acc[n], amd[0], amd[1], amd[2], amd[3], breg[2 * n], breg[2 * n + 1]);

            va0 = vb0; va1 = vb1; va2 = vb2; va3 = vb3;
        }
    }

    // ---- epilogue: per-row first-max argmax over 128 classes ----
    // acc[n][e]: row = w*16 + (e<2 ? lg : lg+8), col = n*8 + lt*2 + (e&1)
#pragma unroll
    for (int h = 0; h < 2; ++h) {
        float best = -3.402823466e38f;
        int bi = 0;
#pragma unroll
        for (int n = 0; n < 16; ++n)
#pragma unroll
            for (int e = 0; e < 2; ++e) {
                float v = acc[n][h * 2 + e];
                int c = n * 8 + lt * 2 + e;
                if (v > best) { best = v; bi = c; }
            }
#pragma unroll
        for (int ofs = 1; ofs < 4; ofs <<= 1) {
            float ov = __shfl_xor_sync(0xffffffffu, best, ofs);
            int oi = __shfl_xor_sync(0xffffffffu, bi, ofs);
            if (ov > best || (ov == best && oi < bi)) { best = ov; bi = oi; }
        }
        if (lt == 0)
            out[blockIdx.x * 128 + w * 16 + h * 8 + lg] = (float)bi;  // float32 output
    }
}

extern "C" void kernel_launch(void* const* d_in, const int* in_sizes, int n_in,
                              void* d_out, int out_size) {
    const float* a = (const float*)d_in[0];
    const float* b = (const float*)d_in[1];

    select_inputs_kernel<<<1, 1>>>(a, b);
    hd_mma_kernel<<<N_DIM / 128, THREADS>>>((float*)d_out);
}

// round 11
// speedup vs baseline: 6.8539x; 1.3195x over previous
#include <cuda_runtime.h>
#include <cuda_fp16.h>
#include <cstdint>

#define N_DIM 16384
#define D_DIM 10240
#define C_DIM 128
#define NUM_CHUNK 160           // chunks of 64 k
#define THREADS 256
#define BSTRIDE 160             // smem bytes per class row (128 data + 32 pad)

// Device-resolved input bindings (selector kernel writes these).
__device__ const float* g_x;
__device__ const float* g_am;

__global__ void select_inputs_kernel(const float* a, const float* b) {
    bool a_is_am = true;
    for (int i = 0; i < 64; ++i) {
        float v = a[i];
        if (v != 1.0f && v != -1.0f) { a_is_am = false; break; }
    }
    g_x  = a_is_am ? b : a;
    g_am = a_is_am ? a : b;
}

static __device__ __forceinline__ uint32_t smem_u32(const void* p) {
    uint32_t a;
    asm("{ .reg .u64 t; cvta.to.shared.u64 t, %1; cvt.u32.u64 %0, t; }" : "=r"(a) : "l"(p));
    return a;
}
static __device__ __forceinline__ uint32_t f16x2_rn(float2 v) {
    __half2 h2 = __float22half2_rn(v);
    return reinterpret_cast<uint32_t&>(h2);
}
// 2-way exact split of a float2 into f16x2 hi/mid; residual <= 2^-23 |x|
static __device__ __forceinline__ void split2(float2 v, uint32_t& h, uint32_t& m) {
    __half2 h2 = __float22half2_rn(v);
    float2 hf = __half22float2(h2);
    __half2 m2 = __float22half2_rn(make_float2(v.x - hf.x, v.y - hf.y));
    h = reinterpret_cast<uint32_t&>(h2);
    m = reinterpret_cast<uint32_t&>(m2);
}

#define MMA16816(d, a0_, a1_, a2_, a3_, b0_, b1_)                                 \
    asm volatile("mma.sync.aligned.m16n8k16.row.col.f32.f16.f16.f32 "             \
                 "{%0,%1,%2,%3}, {%4,%5,%6,%7}, {%8,%9}, {%0,%1,%2,%3};"          \
                 : "+f"((d)[0]), "+f"((d)[1]), "+f"((d)[2]), "+f"((d)[3])         \
                 : "r"(a0_), "r"(a1_), "r"(a2_), "r"(a3_), "r"(b0_), "r"(b1_))

__global__ void __launch_bounds__(THREADS, 1)
hd_mma_kernel(float* __restrict__ out) {
    // B tile for one 64-k chunk: class c, kstep ks (0..3), slot s (0..3).
    // slot s holds fp16 elements {k=ks*16+2s, +1, ks*16+2s+8, +9} as 8 bytes.
    __shared__ __align__(16) char smb[C_DIM * BSTRIDE];
    const uint32_t sb = smem_u32(smb);

    const float* __restrict__ x  = g_x;
    const float* __restrict__ am = g_am;

    const int tid = threadIdx.x;
    const int w = tid >> 5, l = tid & 31;
    const int lg = l >> 2;        // lane group = row within m16 tile (PTX A frag)
    const int lt = l & 3;         // thread in group (PTX A frag)

    // ---- A: direct-gmem fragment pointers (PTX m16n8k16 A layout) ----
    const float* pr0 = x + ((size_t)blockIdx.x * 128 + w * 16 + lg) * D_DIM + lt * 2;
    const float* pr8 = pr0 + (size_t)8 * D_DIM;

    // ---- B producer mapping ----
    const int c0 = tid >> 4;
    const int ks0 = (tid >> 2) & 3;
    const int s0 = tid & 3;
    const float* bsrc0 = am + (size_t)c0 * D_DIM + ks0 * 16 + s0 * 2;
    const uint32_t bdst0 = sb + (uint32_t)(c0 * BSTRIDE + ks0 * 32 + s0 * 8);

    float acc[16][4];
#pragma unroll
    for (int n = 0; n < 16; ++n)
#pragma unroll
        for (int e = 0; e < 4; ++e) acc[n][e] = 0.0f;

    // B register prefetch (one chunk ahead)
    float2 bA[8], bB[8];
#pragma unroll
    for (int i = 0; i < 8; ++i) {
        const float* s = bsrc0 + (size_t)i * 16 * D_DIM;
        bA[i] = *(const float2*)(s);
        bB[i] = *(const float2*)(s + 8);
    }

    // A register prefetch: FULL chunk (4 ksteps x 4 fragments), ping-pong in place.
    // va[j] = {a0={r,k}, a1={r+8,k}, a2={r,k+8}, a3={r+8,k+8}} for kstep j.
    float2 va[4][4];
#pragma unroll
    for (int j = 0; j < 4; ++j) {
        const int off = j * 16;
        va[j][0] = *(const float2*)(pr0 + off);
        va[j][1] = *(const float2*)(pr8 + off);
        va[j][2] = *(const float2*)(pr0 + off + 8);
        va[j][3] = *(const float2*)(pr8 + off + 8);
    }

    for (int ch = 0; ch < NUM_CHUNK; ++ch) {
        __syncthreads();   // prior chunk's LDS reads complete
#pragma unroll
        for (int i = 0; i < 8; ++i) {
            uint32_t p0 = f16x2_rn(bA[i]);   // am is +/-1: fp16 exact
            uint32_t p1 = f16x2_rn(bB[i]);
            asm volatile("st.shared.v2.b32 [%0], {%1, %2};"
                         :: "r"(bdst0 + (uint32_t)(i * 16 * BSTRIDE)), "r"(p0), "r"(p1)
                         : "memory");
        }
        __syncthreads();

        const bool more = (ch + 1 < NUM_CHUNK);
        if (more) {
#pragma unroll
            for (int i = 0; i < 8; ++i) {
                const float* s = bsrc0 + (size_t)i * 16 * D_DIM + (ch + 1) * 64;
                bA[i] = *(const float2*)(s);
                bB[i] = *(const float2*)(s + 8);
            }
        }

#pragma unroll
        for (int j = 0; j < 4; ++j) {
            // Split current A fragments (reads va[j] now, frees the registers)
            uint32_t ah[4], amd[4];
            split2(va[j][0], ah[0], amd[0]);
            split2(va[j][1], ah[1], amd[1]);
            split2(va[j][2], ah[2], amd[2]);
            split2(va[j][3], ah[3], amd[3]);

            // Refill va[j] from NEXT chunk (load->use distance = 4 ksteps)
            if (more) {
                const int off = (ch + 1) * 64 + j * 16;
                va[j][0] = *(const float2*)(pr0 + off);
                va[j][1] = *(const float2*)(pr8 + off);
                va[j][2] = *(const float2*)(pr0 + off + 8);
                va[j][3] = *(const float2*)(pr8 + off + 8);
            }

            // Load ALL 16 B fragment pairs (conflict-free under half-warp phases)
            uint32_t breg[32];
            const uint32_t bbase = sb + (uint32_t)(j * 32 + lt * 8);
#pragma unroll
            for (int n = 0; n < 16; ++n) {
                const int c = n * 8 + lg;
                asm volatile("ld.shared.v2.b32 {%0, %1}, [%2];"
                             : "=r"(breg[2 * n]), "=r"(breg[2 * n + 1])
                             : "r"(bbase + (uint32_t)(c * BSTRIDE)));
            }

            // split-outer / n-inner: consecutive MMAs hit distinct accumulators
#pragma unroll
            for (int n = 0; n < 16; ++n)
                MMA16816(acc[n], ah[0], ah[1], ah[2], ah[3], breg[2 * n], breg[2 * n + 1]);
#pragma unroll
            for (int n = 0; n < 16; ++n)
                MMA16816(acc[n], amd[0], amd[1], amd[2], amd[3], breg[2 * n], breg[2 * n + 1]);
        }
    }

    // ---- epilogue: per-row first-max argmax over 128 classes ----
    // acc[n][e]: row = w*16 + (e<2 ? lg : lg+8), col = n*8 + lt*2 + (e&1)
#pragma unroll
    for (int h = 0; h < 2; ++h) {
        float best = -3.402823466e38f;
        int bi = 0;
#pragma unroll
        for (int n = 0; n < 16; ++n)
#pragma unroll
            for (int e = 0; e < 2; ++e) {
                float v = acc[n][h * 2 + e];
                int c = n * 8 + lt * 2 + e;
                if (v > best) { best = v; bi = c; }
            }
#pragma unroll
        for (int ofs = 1; ofs < 4; ofs <<= 1) {
            float ov = __shfl_xor_sync(0xffffffffu, best, ofs);
            int oi = __shfl_xor_sync(0xffffffffu, bi, ofs);
            if (ov > best || (ov == best && oi < bi)) { best = ov; bi = oi; }
        }
        if (lt == 0)
            out[blockIdx.x * 128 + w * 16 + h * 8 + lg] = (float)bi;  // float32 output
    }
}

extern "C" void kernel_launch(void* const* d_in, const int* in_sizes, int n_in,
                              void* d_out, int out_size) {
    const float* a = (const float*)d_in[0];
    const float* b = (const float*)d_in[1];

    select_inputs_kernel<<<1, 1>>>(a, b);
    hd_mma_kernel<<<N_DIM / 128, THREADS>>>((float*)d_out);
}